// round 1
// baseline (speedup 1.0000x reference)
#include <cuda_runtime.h>
#include <math.h>

// ---------------------------------------------------------------------------
// ZBLRepulsion: per-edge repulsion energy + segment_sum over receivers.
//   N_NODES = 1,000,000   N_EDGES = 32,000,000
//
// Strategy:
//   k0 (1 thread):   softplus params; fold KE*0.5 into normalized c.
//   k1 (1M threads): per-node table float2{ z, d * z^p }  (8MB, L2-resident)
//   memsetAsync:     zero output (harness poisons it)
//   k2 (8M threads): 4 edges/thread, float4/int4 streaming loads,
//                    2x LDG.64 gathers from node table, RED.ADD to out.
// ---------------------------------------------------------------------------

#define KE_CONST 14.399645351950548
#define MAX_NODES 1000000

__device__ float  g_params[10];          // a0..a3, c0..c3 (c*KE*0.5), p, d
__device__ float2 g_node[MAX_NODES];     // {zf, d * zf^p}

// ---- kernel 0: parameter transform (softplus, normalize, fold constants) ----
__global__ void zbl_params_kernel(const float* __restrict__ a_raw,
                                  const float* __restrict__ c_raw,
                                  const float* __restrict__ p_raw,
                                  const float* __restrict__ d_raw) {
    if (threadIdx.x != 0 || blockIdx.x != 0) return;
    double a[4], c[4], csum = 0.0;
#pragma unroll
    for (int k = 0; k < 4; k++) {
        a[k] = log1p(exp((double)a_raw[k]));
        c[k] = log1p(exp((double)c_raw[k]));
        csum += c[k];
    }
    double p = log1p(exp((double)p_raw[0]));
    double d = log1p(exp((double)d_raw[0]));
#pragma unroll
    for (int k = 0; k < 4; k++) {
        g_params[k]     = (float)a[k];
        g_params[4 + k] = (float)(c[k] / csum * KE_CONST * 0.5);
    }
    g_params[8] = (float)p;
    g_params[9] = (float)d;
}

// ---- kernel 1: per-node table {z, d*z^p} ----
__global__ void zbl_node_kernel(const int* __restrict__ node_species,
                                const int* __restrict__ index_to_z,
                                int n_nodes) {
    int i = blockIdx.x * blockDim.x + threadIdx.x;
    if (i >= n_nodes) return;
    float p = g_params[8];
    float d = g_params[9];
    int   z  = index_to_z[node_species[i]];
    float zf = (float)z;
    float zp = powf(zf, p) * d;   // full-precision pow: only 1M of these
    g_node[i] = make_float2(zf, zp);
}

// ---- per-edge body ----
__device__ __forceinline__ void zbl_edge(float dd, float ct, int s, int r,
                                         const float* P,
                                         float* __restrict__ out) {
    float2 ni = g_node[r];
    float2 nj = g_node[s];

    // x' = cutoff * z_i * z_j / (d + 1e-8)    (KE*0.5 folded into c)
    float x = ct * ni.x * nj.x * __fdividef(1.0f, dd + 1e-8f);

    // rzd = d_edge * (d*z_i^p + d*z_j^p)      (d folded into node table)
    float rzd = dd * (ni.y + nj.y);

    float y = P[4] * __expf(-P[0] * rzd)
            + P[5] * __expf(-P[1] * rzd)
            + P[6] * __expf(-P[2] * rzd)
            + P[7] * __expf(-P[3] * rzd);

    // smooth switching function
    float sd = dd * (1.0f / 1.5f);
    float t1 = fmaxf(sd, 1e-8f);
    float t2 = fmaxf(1.0f - sd, 1e-8f);
    float e1 = __expf(-__fdividef(1.0f, t1));   // sigma_d
    float e2 = __expf(-__fdividef(1.0f, t2));   // sigma_1_d
    float w  = __fdividef(e2, e1 + e2);

    atomicAdd(out + r, w * x * y);   // no return use -> RED.ADD
}

// ---- kernel 2: edge loop, 4 edges/thread ----
__global__ void __launch_bounds__(256)
zbl_edge_kernel(const float* __restrict__ distances,
                const float* __restrict__ cutoffs,
                const int* __restrict__ senders,
                const int* __restrict__ receivers,
                float* __restrict__ out,
                int n_edges) {
    float P[8];
#pragma unroll
    for (int k = 0; k < 8; k++) P[k] = g_params[k];

    int i  = blockIdx.x * blockDim.x + threadIdx.x;
    int e0 = i * 4;
    if (e0 >= n_edges) return;

    if (e0 + 3 < n_edges) {
        float4 d4 = *reinterpret_cast<const float4*>(distances + e0);
        float4 c4 = *reinterpret_cast<const float4*>(cutoffs   + e0);
        int4   s4 = *reinterpret_cast<const int4*>(senders    + e0);
        int4   r4 = *reinterpret_cast<const int4*>(receivers  + e0);
        zbl_edge(d4.x, c4.x, s4.x, r4.x, P, out);
        zbl_edge(d4.y, c4.y, s4.y, r4.y, P, out);
        zbl_edge(d4.z, c4.z, s4.z, r4.z, P, out);
        zbl_edge(d4.w, c4.w, s4.w, r4.w, P, out);
    } else {
        for (int e = e0; e < n_edges; e++)
            zbl_edge(distances[e], cutoffs[e], senders[e], receivers[e], P, out);
    }
}

// ---------------------------------------------------------------------------
extern "C" void kernel_launch(void* const* d_in, const int* in_sizes, int n_in,
                              void* d_out, int out_size) {
    const int*   node_species = (const int*)  d_in[0];
    const float* distances    = (const float*)d_in[1];
    const float* cutoffs      = (const float*)d_in[2];
    const int*   senders      = (const int*)  d_in[3];
    const int*   receivers    = (const int*)  d_in[4];
    const int*   index_to_z   = (const int*)  d_in[5];
    const float* a_raw        = (const float*)d_in[6];
    const float* c_raw        = (const float*)d_in[7];
    const float* p_raw        = (const float*)d_in[8];
    const float* d_raw        = (const float*)d_in[9];

    int n_nodes = in_sizes[0];
    int n_edges = in_sizes[1];
    float* out  = (float*)d_out;

    zbl_params_kernel<<<1, 1>>>(a_raw, c_raw, p_raw, d_raw);

    {
        int threads = 256;
        int blocks  = (n_nodes + threads - 1) / threads;
        zbl_node_kernel<<<blocks, threads>>>(node_species, index_to_z, n_nodes);
    }

    cudaMemsetAsync(d_out, 0, (size_t)out_size * sizeof(float), 0);

    {
        int threads = 256;
        int nquads  = (n_edges + 3) / 4;
        int blocks  = (nquads + threads - 1) / threads;
        zbl_edge_kernel<<<blocks, threads>>>(distances, cutoffs, senders,
                                             receivers, out, n_edges);
    }
}

// round 2
// speedup vs baseline: 1.0832x; 1.0832x over previous
#include <cuda_runtime.h>
#include <math.h>

// ---------------------------------------------------------------------------
// ZBLRepulsion: per-edge repulsion energy + segment_sum over receivers.
//   N_NODES = 1,000,000   N_EDGES = 32,000,000   N_SPECIES = 100
//
// LTS-sector model: 16B stream + 2x32B gather sectors + 32B RED sector per
// edge. Shrink the gather target to a 1MB uint8 species array (L1-cacheable),
// resolve z / d*z^p through a 100-entry smem table.
//
// Launches per call: setup(128 thr) -> pack(species->u8, zero out) -> edge.
// ---------------------------------------------------------------------------

#define KE_CONST 14.399645351950548
#define MAX_NODES   1000000
#define MAX_SPECIES 128

__device__ float  g_params[8];                      // a0..a3, c0..3 (*KE/2)
__device__ float2 g_stab[MAX_SPECIES];              // per-species {z, d*z^p}
__device__ uchar4 g_spec4[(MAX_NODES + 3) / 4];     // packed species bytes

__device__ __forceinline__ float softplus_f(float x) {
    return fmaxf(x, 0.0f) + log1pf(expf(-fabsf(x)));
}

// ---- kernel 0: params + 100-entry species table (1 block, 128 threads) ----
__global__ void zbl_setup_kernel(const float* __restrict__ a_raw,
                                 const float* __restrict__ c_raw,
                                 const float* __restrict__ p_raw,
                                 const float* __restrict__ d_raw,
                                 const int* __restrict__ index_to_z,
                                 int n_species) {
    int t = threadIdx.x;
    float p = softplus_f(p_raw[0]);
    float d = softplus_f(d_raw[0]);
    if (t == 0) {
        float c[4], csum = 0.0f;
#pragma unroll
        for (int k = 0; k < 4; k++) {
            g_params[k] = softplus_f(a_raw[k]);
            c[k] = softplus_f(c_raw[k]);
            csum += c[k];
        }
        float scale = (float)(KE_CONST * 0.5) / csum;
#pragma unroll
        for (int k = 0; k < 4; k++) g_params[4 + k] = c[k] * scale;
    }
    if (t < n_species) {
        float zf = (float)index_to_z[t];
        g_stab[t] = make_float2(zf, d * powf(zf, p));
    }
}

// ---- kernel 1: pack species to uint8 + zero output ----
__global__ void zbl_pack_kernel(const int* __restrict__ species,
                                float* __restrict__ out,
                                int n_nodes, int out_n) {
    int q = blockIdx.x * blockDim.x + threadIdx.x;
    int base = q * 4;
    if (base + 3 < n_nodes) {
        int4 s = *reinterpret_cast<const int4*>(species + base);
        g_spec4[q] = make_uchar4((unsigned char)s.x, (unsigned char)s.y,
                                 (unsigned char)s.z, (unsigned char)s.w);
    } else if (base < n_nodes) {
        unsigned char* sp = reinterpret_cast<unsigned char*>(g_spec4);
        for (int k = base; k < n_nodes; k++) sp[k] = (unsigned char)species[k];
    }
    if (base + 3 < out_n) {
        *reinterpret_cast<float4*>(out + base) = make_float4(0.f, 0.f, 0.f, 0.f);
    } else if (base < out_n) {
        for (int k = base; k < out_n; k++) out[k] = 0.0f;
    }
}

// ---- per-edge math (species indices already gathered) ----
__device__ __forceinline__ float zbl_energy(float dd, float ct,
                                            unsigned int si, unsigned int ri,
                                            const float* __restrict__ P,
                                            const float2* __restrict__ stab) {
    float2 nj = stab[si];
    float2 ni = stab[ri];

    float x   = ct * ni.x * nj.x * __fdividef(1.0f, dd + 1e-8f);
    float rzd = dd * (ni.y + nj.y);

    float y = P[4] * __expf(-P[0] * rzd)
            + P[5] * __expf(-P[1] * rzd)
            + P[6] * __expf(-P[2] * rzd)
            + P[7] * __expf(-P[3] * rzd);

    float sd = dd * (1.0f / 1.5f);
    float e1 = __expf(-__fdividef(1.0f, fmaxf(sd, 1e-8f)));
    float e2 = __expf(-__fdividef(1.0f, fmaxf(1.0f - sd, 1e-8f)));
    float w  = __fdividef(e2, e1 + e2);

    return w * x * y;
}

// ---- kernel 2: edge loop, 4 edges/thread ----
__global__ void __launch_bounds__(256)
zbl_edge_kernel(const float* __restrict__ distances,
                const float* __restrict__ cutoffs,
                const int* __restrict__ senders,
                const int* __restrict__ receivers,
                float* __restrict__ out,
                int n_edges, int n_species) {
    __shared__ float2 stab[MAX_SPECIES];
    for (int t = threadIdx.x; t < n_species; t += blockDim.x)
        stab[t] = g_stab[t];
    float P[8];
#pragma unroll
    for (int k = 0; k < 8; k++) P[k] = g_params[k];
    __syncthreads();

    const unsigned char* spec = reinterpret_cast<const unsigned char*>(g_spec4);

    int i  = blockIdx.x * blockDim.x + threadIdx.x;
    int e0 = i * 4;
    if (e0 >= n_edges) return;

    if (e0 + 3 < n_edges) {
        // streaming loads: L2-only (preserve L1 for the species gathers)
        float4 d4 = __ldcg(reinterpret_cast<const float4*>(distances + e0));
        float4 c4 = __ldcg(reinterpret_cast<const float4*>(cutoffs   + e0));
        int4   s4 = __ldcg(reinterpret_cast<const int4*>(senders    + e0));
        int4   r4 = __ldcg(reinterpret_cast<const int4*>(receivers  + e0));

        // issue all 8 gathers up front (MLP)
        unsigned int sa = __ldg(spec + s4.x), ra = __ldg(spec + r4.x);
        unsigned int sb = __ldg(spec + s4.y), rb = __ldg(spec + r4.y);
        unsigned int sc = __ldg(spec + s4.z), rc = __ldg(spec + r4.z);
        unsigned int sd_ = __ldg(spec + s4.w), rd = __ldg(spec + r4.w);

        float va = zbl_energy(d4.x, c4.x, sa, ra, P, stab);
        float vb = zbl_energy(d4.y, c4.y, sb, rb, P, stab);
        float vc = zbl_energy(d4.z, c4.z, sc, rc, P, stab);
        float vd = zbl_energy(d4.w, c4.w, sd_, rd, P, stab);

        atomicAdd(out + r4.x, va);
        atomicAdd(out + r4.y, vb);
        atomicAdd(out + r4.z, vc);
        atomicAdd(out + r4.w, vd);
    } else {
        for (int e = e0; e < n_edges; e++) {
            unsigned int si = spec[senders[e]];
            unsigned int ri = spec[receivers[e]];
            float v = zbl_energy(distances[e], cutoffs[e], si, ri, P, stab);
            atomicAdd(out + receivers[e], v);
        }
    }
}

// ---------------------------------------------------------------------------
extern "C" void kernel_launch(void* const* d_in, const int* in_sizes, int n_in,
                              void* d_out, int out_size) {
    const int*   node_species = (const int*)  d_in[0];
    const float* distances    = (const float*)d_in[1];
    const float* cutoffs      = (const float*)d_in[2];
    const int*   senders      = (const int*)  d_in[3];
    const int*   receivers    = (const int*)  d_in[4];
    const int*   index_to_z   = (const int*)  d_in[5];
    const float* a_raw        = (const float*)d_in[6];
    const float* c_raw        = (const float*)d_in[7];
    const float* p_raw        = (const float*)d_in[8];
    const float* d_raw        = (const float*)d_in[9];

    int n_nodes   = in_sizes[0];
    int n_edges   = in_sizes[1];
    int n_species = in_sizes[5];
    float* out    = (float*)d_out;

    zbl_setup_kernel<<<1, 128>>>(a_raw, c_raw, p_raw, d_raw,
                                 index_to_z, n_species);

    {
        int n = (n_nodes > out_size) ? n_nodes : out_size;
        int quads   = (n + 3) / 4;
        int threads = 256;
        int blocks  = (quads + threads - 1) / threads;
        zbl_pack_kernel<<<blocks, threads>>>(node_species, out,
                                             n_nodes, out_size);
    }

    {
        int threads = 256;
        int quads   = (n_edges + 3) / 4;
        int blocks  = (quads + threads - 1) / threads;
        zbl_edge_kernel<<<blocks, threads>>>(distances, cutoffs, senders,
                                             receivers, out, n_edges,
                                             n_species);
    }
}